// round 5
// baseline (speedup 1.0000x reference)
// Linear1d: out = (x @ W^T) / sqrt(2048) + 0.1*b
// int8 fixed-point 3-term split (x ~ s*(128a+b)) using mma.sync.m16n8k32.s8,
// exact int32 accumulation, 4-stage cp.async pipeline. Base-sm_103 legal.
#include <cuda_runtime.h>
#include <cuda_bf16.h>
#include <cstdint>

#define XN 16384
#define KD 2048
#define ON 2048

static constexpr int BM = 128, BN = 128, BK = 64;  // BK in int8 elems (64B rows)
static constexpr int NCH = KD / BK;                // 32
static constexpr int ROWB = 80;                    // 64B data + 16B pad (bank-spread)
static constexpr int PLANE = 128 * ROWB;           // 10240
static constexpr int PL_Aa = 0;
static constexpr int PL_Ab = PLANE;
static constexpr int PL_Ba = 2 * PLANE;
static constexpr int PL_Bb = 3 * PLANE;
static constexpr int STAGE = 4 * PLANE;            // 40960
static constexpr int NSTG = 4;
static constexpr int SMEM_TOTAL = NSTG * STAGE;    // 163840

// int8 planes: [0]=hi(a), [1]=lo(b); per-row scales
__device__ int8_t gA[2][(size_t)XN * KD];   // 67 MB
__device__ int8_t gB[2][(size_t)ON * KD];   // 8.4 MB
__device__ float  gSx[XN];
__device__ float  gSw[ON];

// ---------------- helpers ----------------
__device__ __forceinline__ uint32_t smem_u32(const void* p) {
    uint32_t a;
    asm("{ .reg .u64 t; cvta.to.shared.u64 t, %1; cvt.u32.u64 %0, t; }" : "=r"(a) : "l"(p));
    return a;
}
__device__ __forceinline__ void cp16(uint32_t dst, const void* src) {
    asm volatile("cp.async.cg.shared.global [%0], [%1], 16;" :: "r"(dst), "l"(src));
}
__device__ __forceinline__ void ldm_x4(uint32_t* r, uint32_t addr) {
    asm volatile("ldmatrix.sync.aligned.m8n8.x4.shared.b16 {%0,%1,%2,%3}, [%4];"
                 : "=r"(r[0]), "=r"(r[1]), "=r"(r[2]), "=r"(r[3])
                 : "r"(addr));
}
__device__ __forceinline__ void mma_s8(int* c, const uint32_t* a, const uint32_t* b) {
    asm volatile(
        "mma.sync.aligned.m16n8k32.row.col.s32.s8.s8.s32 "
        "{%0,%1,%2,%3}, {%4,%5,%6,%7}, {%8,%9}, {%0,%1,%2,%3};"
        : "+r"(c[0]), "+r"(c[1]), "+r"(c[2]), "+r"(c[3])
        : "r"(a[0]), "r"(a[1]), "r"(a[2]), "r"(a[3]), "r"(b[0]), "r"(b[1]));
}
__device__ __forceinline__ uint32_t pack4(float f0, float f1, float f2, float f3) {
    int i0 = __float2int_rn(f0), i1 = __float2int_rn(f1);
    int i2 = __float2int_rn(f2), i3 = __float2int_rn(f3);
    return (i0 & 0xFF) | ((i1 & 0xFF) << 8) | ((i2 & 0xFF) << 16) | ((i3 & 0xFF) << 24);
}

// ---------------- quantize: fp32 row -> (a,b) int8 planes + scale ----------------
__global__ void __launch_bounds__(256) quant_kernel(const float* __restrict__ src, int which) {
    int row = blockIdx.x, tid = threadIdx.x;
    const float* rp = src + (size_t)row * KD;
    float4 v0 = ((const float4*)rp)[tid * 2];
    float4 v1 = ((const float4*)rp)[tid * 2 + 1];
    float m = fmaxf(fmaxf(fmaxf(fabsf(v0.x), fabsf(v0.y)), fmaxf(fabsf(v0.z), fabsf(v0.w))),
                    fmaxf(fmaxf(fabsf(v1.x), fabsf(v1.y)), fmaxf(fabsf(v1.z), fabsf(v1.w))));
#pragma unroll
    for (int off = 16; off > 0; off >>= 1)
        m = fmaxf(m, __shfl_xor_sync(0xFFFFFFFFu, m, off));
    __shared__ float red[8];
    __shared__ float sS;
    if ((tid & 31) == 0) red[tid >> 5] = m;
    __syncthreads();
    if (tid == 0) {
        float mm = red[0];
#pragma unroll
        for (int i = 1; i < 8; i++) mm = fmaxf(mm, red[i]);
        float s = fmaxf(mm, 1e-20f) * (1.0f / 16256.0f);
        sS = s;
        if (which) gSw[row] = s; else gSx[row] = s;
    }
    __syncthreads();
    float inv = 1.0f / sS;
    float q[8] = {v0.x * inv, v0.y * inv, v0.z * inv, v0.w * inv,
                  v1.x * inv, v1.y * inv, v1.z * inv, v1.w * inv};
    float af[8], bf[8];
#pragma unroll
    for (int i = 0; i < 8; i++) {
        af[i] = rintf(q[i] * (1.0f / 128.0f));
        bf[i] = rintf(q[i] - 128.0f * af[i]);
    }
    uint2 A, B;
    A.x = pack4(af[0], af[1], af[2], af[3]); A.y = pack4(af[4], af[5], af[6], af[7]);
    B.x = pack4(bf[0], bf[1], bf[2], bf[3]); B.y = pack4(bf[4], bf[5], bf[6], bf[7]);
    size_t off = (size_t)row * KD + (size_t)tid * 8;
    int8_t* pa = which ? gB[0] : gA[0];
    int8_t* pb = which ? gB[1] : gA[1];
    *(uint2*)(pa + off) = A;
    *(uint2*)(pb + off) = B;
}

// ---------------- stage loader: 4 planes x 128 rows x 64B ----------------
__device__ __forceinline__ void load_stage(uint32_t sb, int st, int kc,
                                           int m0, int n0, int tid) {
    int r = tid & 127, h = tid >> 7;
    uint32_t base = sb + (uint32_t)st * STAGE;
    const int8_t* sAa = &gA[0][(size_t)(m0 + r) * KD + kc];
    const int8_t* sAb = &gA[1][(size_t)(m0 + r) * KD + kc];
    const int8_t* sBa = &gB[0][(size_t)(n0 + r) * KD + kc];
    const int8_t* sBb = &gB[1][(size_t)(n0 + r) * KD + kc];
    uint32_t rb = base + (uint32_t)(r * ROWB);
#pragma unroll
    for (int j = 2 * h; j < 2 * h + 2; j++) {
        uint32_t d = (uint32_t)(j * 16);
        cp16(rb + PL_Aa + d, sAa + j * 16);
        cp16(rb + PL_Ab + d, sAb + j * 16);
        cp16(rb + PL_Ba + d, sBa + j * 16);
        cp16(rb + PL_Bb + d, sBb + j * 16);
    }
    asm volatile("cp.async.commit_group;" ::: "memory");
}

// ---------------- GEMM: 128x128 tile, 8 warps of 64x32, 3 s8 terms ----------------
__global__ void __launch_bounds__(256, 1) gemm_kernel(const float* __restrict__ bias,
                                                      float* __restrict__ out) {
    extern __shared__ char smem[];
    uint32_t sb = smem_u32(smem);
    int tid = threadIdx.x, l = tid & 31, wid = tid >> 5;
    int wm = wid & 1, wn = wid >> 1;  // 2 x 4 warp grid (64x32 each)
    int m0 = blockIdx.y * BM, n0 = blockIdx.x * BN;

    int acc1[4][4][4], acc2[4][4][4];
#pragma unroll
    for (int i = 0; i < 4; i++)
#pragma unroll
        for (int j = 0; j < 4; j++)
#pragma unroll
            for (int q = 0; q < 4; q++) { acc1[i][j][q] = 0; acc2[i][j][q] = 0; }

    load_stage(sb, 0, 0, m0, n0, tid);
    load_stage(sb, 1, BK, m0, n0, tid);
    load_stage(sb, 2, 2 * BK, m0, n0, tid);

    // ldmatrix lane geometry (same byte math as bf16 k16, granule now 4B/k32)
    int g = l >> 3, lr = l & 7;
    uint32_t a_row = (uint32_t)(wm * 64 + ((g & 1) << 3) + lr);
    uint32_t a_kb0 = (uint32_t)((g >> 1) << 4);
    uint32_t b_row = (uint32_t)(wn * 32 + ((g >> 1) << 3) + lr);
    uint32_t b_kb0 = (uint32_t)((g & 1) << 4);

    for (int c = 0; c < NCH; c++) {
        if (c <= NCH - 3)      asm volatile("cp.async.wait_group 2;" ::: "memory");
        else if (c == NCH - 2) asm volatile("cp.async.wait_group 1;" ::: "memory");
        else                   asm volatile("cp.async.wait_group 0;" ::: "memory");
        __syncthreads();
        if (c + 3 < NCH) load_stage(sb, (c + 3) & 3, (c + 3) * BK, m0, n0, tid);

        uint32_t base = sb + (uint32_t)(c & 3) * STAGE;
#pragma unroll
        for (int ks = 0; ks < 2; ks++) {  // two k32 steps per 64B chunk
            uint32_t Aa[4][4], Ab[4][4], Ba[2][4], Bb[2][4];
            uint32_t akb = (uint32_t)(ks * 32) + a_kb0;
            uint32_t bkb = (uint32_t)(ks * 32) + b_kb0;
#pragma unroll
            for (int mf = 0; mf < 4; mf++) {
                uint32_t ra = base + (a_row + (uint32_t)(mf * 16)) * ROWB + akb;
                ldm_x4(Aa[mf], ra + PL_Aa);
                ldm_x4(Ab[mf], ra + PL_Ab);
            }
#pragma unroll
            for (int nf = 0; nf < 2; nf++) {
                uint32_t rb = base + (b_row + (uint32_t)(nf * 16)) * ROWB + bkb;
                ldm_x4(Ba[nf], rb + PL_Ba);
                ldm_x4(Bb[nf], rb + PL_Bb);
            }
#pragma unroll
            for (int mf = 0; mf < 4; mf++)
#pragma unroll
                for (int nf = 0; nf < 4; nf++) {
                    const uint32_t* ba = &Ba[nf >> 1][(nf & 1) * 2];
                    const uint32_t* bb = &Bb[nf >> 1][(nf & 1) * 2];
                    mma_s8(acc1[mf][nf], Aa[mf], ba);   // ac  (x 2^14)
                    mma_s8(acc2[mf][nf], Aa[mf], bb);   // ad  (x 2^7)
                    mma_s8(acc2[mf][nf], Ab[mf], ba);   // bc  (x 2^7)
                }
        }
    }

    // epilogue: out = (acc1*2^14 + acc2*2^7) * sx*sw*S + 0.1*bias
    const float S = 0.02209708691207961f;  // 1/sqrt(2048)
    int col_base = n0 + wn * 32 + (l & 3) * 2;
    int row_base = m0 + wm * 64 + (l >> 2);
    float sx0[4], sx1[4];
#pragma unroll
    for (int mf = 0; mf < 4; mf++) {
        sx0[mf] = gSx[row_base + mf * 16] * S;
        sx1[mf] = gSx[row_base + mf * 16 + 8] * S;
    }
#pragma unroll
    for (int nf = 0; nf < 4; nf++) {
        int colx = col_base + nf * 8;
        float2 sw2 = *(const float2*)(gSw + colx);
        float2 bv;
        bv.x = 0.1f * __ldg(bias + colx);
        bv.y = 0.1f * __ldg(bias + colx + 1);
#pragma unroll
        for (int mf = 0; mf < 4; mf++) {
            float f0 = (float)acc1[mf][nf][0] * 16384.0f + (float)acc2[mf][nf][0] * 128.0f;
            float f1 = (float)acc1[mf][nf][1] * 16384.0f + (float)acc2[mf][nf][1] * 128.0f;
            float f2 = (float)acc1[mf][nf][2] * 16384.0f + (float)acc2[mf][nf][2] * 128.0f;
            float f3 = (float)acc1[mf][nf][3] * 16384.0f + (float)acc2[mf][nf][3] * 128.0f;
            float2 v0, v1;
            v0.x = f0 * (sx0[mf] * sw2.x) + bv.x;
            v0.y = f1 * (sx0[mf] * sw2.y) + bv.y;
            v1.x = f2 * (sx1[mf] * sw2.x) + bv.x;
            v1.y = f3 * (sx1[mf] * sw2.y) + bv.y;
            size_t r0 = (size_t)(row_base + mf * 16) * ON + colx;
            *(float2*)(out + r0) = v0;
            *(float2*)(out + r0 + (size_t)8 * ON) = v1;
        }
    }
}

// ---------------- launch ----------------
extern "C" void kernel_launch(void* const* d_in, const int* in_sizes, int n_in,
                              void* d_out, int out_size) {
    (void)in_sizes; (void)n_in; (void)out_size;
    const float* x = (const float*)d_in[0];
    const float* w = (const float*)d_in[1];
    const float* b = (const float*)d_in[2];
    float* out = (float*)d_out;

    cudaFuncSetAttribute(gemm_kernel, cudaFuncAttributeMaxDynamicSharedMemorySize, SMEM_TOTAL);

    quant_kernel<<<XN, 256>>>(x, 0);
    quant_kernel<<<ON, 256>>>(w, 1);

    dim3 grid(ON / BN, XN / BM);  // (16, 128): n-tiles fastest for W reuse in L2
    gemm_kernel<<<grid, 256, SMEM_TOTAL>>>(b, out);
}

// round 6
// speedup vs baseline: 2.7054x; 2.7054x over previous
// Linear1d: out = (x @ W^T) / sqrt(2048) + 0.1*b
// fp16 single-term HMMA (m16n8k16.f32.f16.f16.f32, f32 accum => only input-rounding
// error ~2e-4 norm), 4-stage cp.async pipeline, 1 sync/chunk. Base-sm_103 legal.
#include <cuda_runtime.h>
#include <cuda_fp16.h>
#include <cstdint>

#define XN 16384
#define KD 2048
#define ON 2048

static constexpr int BM = 128, BN = 128, BK = 64;  // BK fp16 elems (128B rows)
static constexpr int NCH = KD / BK;                // 32
static constexpr int PL_A = 0;                      // 128 rows x 128B
static constexpr int PL_B = 16384;                  // 128 rows x 128B
static constexpr int STAGE = 32768;
static constexpr int NSTG = 4;
static constexpr int SMEM_TOTAL = NSTG * STAGE;     // 128 KB

// fp16 planes (device scratch)
__device__ __half hA[(size_t)XN * KD];  // 67 MB
__device__ __half hB[(size_t)ON * KD];  // 8.4 MB

// ---------------- helpers ----------------
__device__ __forceinline__ uint32_t smem_u32(const void* p) {
    uint32_t a;
    asm("{ .reg .u64 t; cvta.to.shared.u64 t, %1; cvt.u32.u64 %0, t; }" : "=r"(a) : "l"(p));
    return a;
}
__device__ __forceinline__ void cp16(uint32_t dst, const void* src) {
    asm volatile("cp.async.cg.shared.global [%0], [%1], 16;" :: "r"(dst), "l"(src));
}
__device__ __forceinline__ void ldm_x4(uint32_t* r, uint32_t addr) {
    asm volatile("ldmatrix.sync.aligned.m8n8.x4.shared.b16 {%0,%1,%2,%3}, [%4];"
                 : "=r"(r[0]), "=r"(r[1]), "=r"(r[2]), "=r"(r[3])
                 : "r"(addr));
}
__device__ __forceinline__ void mma_f16(float* c, const uint32_t* a, const uint32_t* b) {
    asm volatile(
        "mma.sync.aligned.m16n8k16.row.col.f32.f16.f16.f32 "
        "{%0,%1,%2,%3}, {%4,%5,%6,%7}, {%8,%9}, {%0,%1,%2,%3};"
        : "+f"(c[0]), "+f"(c[1]), "+f"(c[2]), "+f"(c[3])
        : "r"(a[0]), "r"(a[1]), "r"(a[2]), "r"(a[3]), "r"(b[0]), "r"(b[1]));
}

// ---------------- convert: fp32 -> fp16 plane ----------------
__global__ void __launch_bounds__(256) convert_kernel(const float* __restrict__ src,
                                                      int n4, int which) {
    size_t i = (size_t)blockIdx.x * blockDim.x + threadIdx.x;
    if (i >= (size_t)n4) return;
    __half* dst = which ? hB : hA;
    float4 v = ((const float4*)src)[i];
    __half2 p0 = __floats2half2_rn(v.x, v.y);
    __half2 p1 = __floats2half2_rn(v.z, v.w);
    uint2 o;
    o.x = *(const uint32_t*)&p0;
    o.y = *(const uint32_t*)&p1;
    ((uint2*)dst)[i] = o;
}

// ---------------- stage loader: 2 planes x 128 rows x 128B ----------------
__device__ __forceinline__ void load_stage(uint32_t sb, int st, int kc,
                                           int m0, int n0, int tid) {
    int r = tid & 127, h = tid >> 7;
    uint32_t base = sb + (uint32_t)st * STAGE;
    uint32_t sw = (uint32_t)((r & 7) << 4);  // SW128 xor
    const __half* sA = &hA[(size_t)(m0 + r) * KD + kc];
    const __half* sB = &hB[(size_t)(n0 + r) * KD + kc];
    uint32_t rb = base + (uint32_t)(r * 128);
#pragma unroll
    for (int j = 0; j < 4; j++) {
        int jc = h * 4 + j;                       // 16B chunk within 128B row
        uint32_t d = ((uint32_t)(jc * 16)) ^ sw;
        cp16(rb + PL_A + d, (const char*)sA + jc * 16);
        cp16(rb + PL_B + d, (const char*)sB + jc * 16);
    }
    asm volatile("cp.async.commit_group;" ::: "memory");
}

// ---------------- GEMM: 128x128 tile, 8 warps of 64x32 ----------------
__global__ void __launch_bounds__(256, 1) gemm_kernel(const float* __restrict__ bias,
                                                      float* __restrict__ out) {
    extern __shared__ char smem[];
    uint32_t sb = smem_u32(smem);
    int tid = threadIdx.x, l = tid & 31, wid = tid >> 5;
    int wm = wid & 1, wn = wid >> 1;  // 2 x 4 warp grid (64x32 each)
    int m0 = blockIdx.y * BM, n0 = blockIdx.x * BN;

    float acc[4][4][4];
#pragma unroll
    for (int i = 0; i < 4; i++)
#pragma unroll
        for (int j = 0; j < 4; j++)
#pragma unroll
            for (int q = 0; q < 4; q++) acc[i][j][q] = 0.f;

    load_stage(sb, 0, 0, m0, n0, tid);
    load_stage(sb, 1, BK, m0, n0, tid);
    load_stage(sb, 2, 2 * BK, m0, n0, tid);

    // ldmatrix lane geometry (proven in R3): 128B rows, SW128 xor
    int g = l >> 3, lr = l & 7;
    uint32_t swx = (uint32_t)(lr << 4);
    uint32_t a_row = (uint32_t)(wm * 64 + ((g & 1) << 3) + lr);
    uint32_t a_kb0 = (uint32_t)((g >> 1) << 4);
    uint32_t b_row = (uint32_t)(wn * 32 + ((g >> 1) << 3) + lr);
    uint32_t b_kb0 = (uint32_t)((g & 1) << 4);

    for (int c = 0; c < NCH; c++) {
        if (c <= NCH - 3)      asm volatile("cp.async.wait_group 2;" ::: "memory");
        else if (c == NCH - 2) asm volatile("cp.async.wait_group 1;" ::: "memory");
        else                   asm volatile("cp.async.wait_group 0;" ::: "memory");
        __syncthreads();
        if (c + 3 < NCH) load_stage(sb, (c + 3) & 3, (c + 3) * BK, m0, n0, tid);

        uint32_t base = sb + (uint32_t)(c & 3) * STAGE;
#pragma unroll
        for (int ks = 0; ks < 4; ks++) {  // four k16 steps per 64-elem chunk
            uint32_t A[4][4], B[2][4];
            uint32_t akb = (((uint32_t)(ks * 32)) + a_kb0) ^ swx;
            uint32_t bkb = (((uint32_t)(ks * 32)) + b_kb0) ^ swx;
#pragma unroll
            for (int mf = 0; mf < 4; mf++)
                ldm_x4(A[mf], base + PL_A + ((a_row + (uint32_t)(mf * 16)) << 7) + akb);
#pragma unroll
            for (int nf = 0; nf < 2; nf++)
                ldm_x4(B[nf], base + PL_B + ((b_row + (uint32_t)(nf * 16)) << 7) + bkb);
#pragma unroll
            for (int mf = 0; mf < 4; mf++)
#pragma unroll
                for (int nf = 0; nf < 4; nf++)
                    mma_f16(acc[mf][nf], A[mf], &B[nf >> 1][(nf & 1) * 2]);
        }
    }

    // epilogue: scale + 0.1*bias, float2 stores
    const float S = 0.02209708691207961f;  // 1/sqrt(2048)
    int col_base = n0 + wn * 32 + (l & 3) * 2;
    int row_base = m0 + wm * 64 + (l >> 2);
#pragma unroll
    for (int mf = 0; mf < 4; mf++) {
#pragma unroll
        for (int nf = 0; nf < 4; nf++) {
            int colx = col_base + nf * 8;
            float2 bv = *(const float2*)(bias + colx);
            float2 v0, v1;
            v0.x = acc[mf][nf][0] * S + 0.1f * bv.x;
            v0.y = acc[mf][nf][1] * S + 0.1f * bv.y;
            v1.x = acc[mf][nf][2] * S + 0.1f * bv.x;
            v1.y = acc[mf][nf][3] * S + 0.1f * bv.y;
            size_t r0 = (size_t)(row_base + mf * 16) * ON + colx;
            *(float2*)(out + r0) = v0;
            *(float2*)(out + r0 + (size_t)8 * ON) = v1;
        }
    }
}

// ---------------- launch ----------------
extern "C" void kernel_launch(void* const* d_in, const int* in_sizes, int n_in,
                              void* d_out, int out_size) {
    (void)in_sizes; (void)n_in; (void)out_size;
    const float* x = (const float*)d_in[0];
    const float* w = (const float*)d_in[1];
    const float* b = (const float*)d_in[2];
    float* out = (float*)d_out;

    cudaFuncSetAttribute(gemm_kernel, cudaFuncAttributeMaxDynamicSharedMemorySize, SMEM_TOTAL);

    int nx4 = (XN * KD) / 4;  // 8388608
    int nw4 = (ON * KD) / 4;  // 1048576
    convert_kernel<<<nx4 / 256, 256>>>(x, nx4, 0);
    convert_kernel<<<nw4 / 256, 256>>>(w, nw4, 1);

    dim3 grid(ON / BN, XN / BM);  // (16, 128): n-tiles fastest for W reuse in L2
    gemm_kernel<<<grid, 256, SMEM_TOTAL>>>(b, out);
}

// round 9
// speedup vs baseline: 4.5801x; 1.6929x over previous
// Linear1d: out = (x @ W^T) / sqrt(2048) + 0.1*b
// fp16 single-term HMMA + 3-stage cp.async pipeline, 2 CTAs/SM for latency hiding.
#include <cuda_runtime.h>
#include <cuda_fp16.h>
#include <cstdint>

#define XN 16384
#define KD 2048
#define ON 2048

static constexpr int BM = 128, BN = 128, BK = 64;  // BK fp16 elems (128B rows)
static constexpr int NCH = KD / BK;                // 32
static constexpr int PL_A = 0;                      // 128 rows x 128B
static constexpr int PL_B = 16384;                  // 128 rows x 128B
static constexpr int STAGE = 32768;
static constexpr int NSTG = 3;
static constexpr int SMEM_TOTAL = NSTG * STAGE;     // 96 KB -> 2 CTAs/SM

// fp16 planes (device scratch)
__device__ __half hA[(size_t)XN * KD];  // 67 MB
__device__ __half hB[(size_t)ON * KD];  // 8.4 MB

// ---------------- helpers ----------------
__device__ __forceinline__ uint32_t smem_u32(const void* p) {
    uint32_t a;
    asm("{ .reg .u64 t; cvta.to.shared.u64 t, %1; cvt.u32.u64 %0, t; }" : "=r"(a) : "l"(p));
    return a;
}
__device__ __forceinline__ void cp16(uint32_t dst, const void* src) {
    asm volatile("cp.async.cg.shared.global [%0], [%1], 16;" :: "r"(dst), "l"(src));
}
__device__ __forceinline__ void ldm_x4(uint32_t* r, uint32_t addr) {
    asm volatile("ldmatrix.sync.aligned.m8n8.x4.shared.b16 {%0,%1,%2,%3}, [%4];"
                 : "=r"(r[0]), "=r"(r[1]), "=r"(r[2]), "=r"(r[3])
                 : "r"(addr));
}
__device__ __forceinline__ void mma_f16(float* c, const uint32_t* a, const uint32_t* b) {
    asm volatile(
        "mma.sync.aligned.m16n8k16.row.col.f32.f16.f16.f32 "
        "{%0,%1,%2,%3}, {%4,%5,%6,%7}, {%8,%9}, {%0,%1,%2,%3};"
        : "+f"(c[0]), "+f"(c[1]), "+f"(c[2]), "+f"(c[3])
        : "r"(a[0]), "r"(a[1]), "r"(a[2]), "r"(a[3]), "r"(b[0]), "r"(b[1]));
}

// ---------------- convert: fp32 -> fp16 plane ----------------
__global__ void __launch_bounds__(256) convert_kernel(const float* __restrict__ src,
                                                      int n4, int which) {
    size_t i = (size_t)blockIdx.x * blockDim.x + threadIdx.x;
    if (i >= (size_t)n4) return;
    __half* dst = which ? hB : hA;
    float4 v = ((const float4*)src)[i];
    __half2 p0 = __floats2half2_rn(v.x, v.y);
    __half2 p1 = __floats2half2_rn(v.z, v.w);
    uint2 o;
    o.x = *(const uint32_t*)&p0;
    o.y = *(const uint32_t*)&p1;
    ((uint2*)dst)[i] = o;
}

// ---------------- stage loader: 2 planes x 128 rows x 128B ----------------
__device__ __forceinline__ void load_stage(uint32_t sb, int st, int kc,
                                           int m0, int n0, int tid) {
    int r = tid & 127, h = tid >> 7;
    uint32_t base = sb + (uint32_t)st * STAGE;
    uint32_t sw = (uint32_t)((r & 7) << 4);  // SW128 xor
    const __half* sA = &hA[(size_t)(m0 + r) * KD + kc];
    const __half* sB = &hB[(size_t)(n0 + r) * KD + kc];
    uint32_t rb = base + (uint32_t)(r * 128);
#pragma unroll
    for (int j = 0; j < 4; j++) {
        int jc = h * 4 + j;                       // 16B chunk within 128B row
        uint32_t d = ((uint32_t)(jc * 16)) ^ sw;
        cp16(rb + PL_A + d, (const char*)sA + jc * 16);
        cp16(rb + PL_B + d, (const char*)sB + jc * 16);
    }
    asm volatile("cp.async.commit_group;" ::: "memory");
}

// ---------------- GEMM: 128x128 tile, 8 warps of 64x32, 2 CTAs/SM ----------------
__global__ void __launch_bounds__(256, 2) gemm_kernel(const float* __restrict__ bias,
                                                      float* __restrict__ out) {
    extern __shared__ char smem[];
    uint32_t sb = smem_u32(smem);
    int tid = threadIdx.x, l = tid & 31, wid = tid >> 5;
    int wm = wid & 1, wn = wid >> 1;  // 2 x 4 warp grid (64x32 each)
    int m0 = blockIdx.y * BM, n0 = blockIdx.x * BN;

    float acc[4][4][4];
#pragma unroll
    for (int i = 0; i < 4; i++)
#pragma unroll
        for (int j = 0; j < 4; j++)
#pragma unroll
            for (int q = 0; q < 4; q++) acc[i][j][q] = 0.f;

    load_stage(sb, 0, 0, m0, n0, tid);
    load_stage(sb, 1, BK, m0, n0, tid);

    // ldmatrix lane geometry: 128B rows, SW128 xor
    int g = l >> 3, lr = l & 7;
    uint32_t swx = (uint32_t)(lr << 4);
    uint32_t a_row = (uint32_t)(wm * 64 + ((g & 1) << 3) + lr);
    uint32_t a_kb0 = (uint32_t)((g >> 1) << 4);
    uint32_t b_row = (uint32_t)(wn * 32 + ((g >> 1) << 3) + lr);
    uint32_t b_kb0 = (uint32_t)((g & 1) << 4);

    for (int c = 0; c < NCH; c++) {
        if (c + 1 < NCH) asm volatile("cp.async.wait_group 1;" ::: "memory");
        else             asm volatile("cp.async.wait_group 0;" ::: "memory");
        __syncthreads();
        if (c + 2 < NCH) load_stage(sb, (c + 2) % 3, (c + 2) * BK, m0, n0, tid);

        uint32_t base = sb + (uint32_t)(c % 3) * STAGE;
#pragma unroll
        for (int ks = 0; ks < 4; ks++) {  // four k16 steps per 64-elem chunk
            uint32_t A[4][4], B[2][4];
            uint32_t akb = (((uint32_t)(ks * 32)) + a_kb0) ^ swx;
            uint32_t bkb = (((uint32_t)(ks * 32)) + b_kb0) ^ swx;
#pragma unroll
            for (int mf = 0; mf < 4; mf++)
                ldm_x4(A[mf], base + PL_A + ((a_row + (uint32_t)(mf * 16)) << 7) + akb);
#pragma unroll
            for (int nf = 0; nf < 2; nf++)
                ldm_x4(B[nf], base + PL_B + ((b_row + (uint32_t)(nf * 16)) << 7) + bkb);
#pragma unroll
            for (int mf = 0; mf < 4; mf++)
#pragma unroll
                for (int nf = 0; nf < 4; nf++)
                    mma_f16(acc[mf][nf], A[mf], &B[nf >> 1][(nf & 1) * 2]);
        }
    }

    // epilogue: scale + 0.1*bias, float2 stores
    const float S = 0.02209708691207961f;  // 1/sqrt(2048)
    int col_base = n0 + wn * 32 + (l & 3) * 2;
    int row_base = m0 + wm * 64 + (l >> 2);
#pragma unroll
    for (int mf = 0; mf < 4; mf++) {
#pragma unroll
        for (int nf = 0; nf < 4; nf++) {
            int colx = col_base + nf * 8;
            float2 bv = *(const float2*)(bias + colx);
            float2 v0, v1;
            v0.x = acc[mf][nf][0] * S + 0.1f * bv.x;
            v0.y = acc[mf][nf][1] * S + 0.1f * bv.y;
            v1.x = acc[mf][nf][2] * S + 0.1f * bv.x;
            v1.y = acc[mf][nf][3] * S + 0.1f * bv.y;
            size_t r0 = (size_t)(row_base + mf * 16) * ON + colx;
            *(float2*)(out + r0) = v0;
            *(float2*)(out + r0 + (size_t)8 * ON) = v1;
        }
    }
}

// ---------------- launch ----------------
extern "C" void kernel_launch(void* const* d_in, const int* in_sizes, int n_in,
                              void* d_out, int out_size) {
    (void)in_sizes; (void)n_in; (void)out_size;
    const float* x = (const float*)d_in[0];
    const float* w = (const float*)d_in[1];
    const float* b = (const float*)d_in[2];
    float* out = (float*)d_out;

    cudaFuncSetAttribute(gemm_kernel, cudaFuncAttributeMaxDynamicSharedMemorySize, SMEM_TOTAL);

    int nx4 = (XN * KD) / 4;  // 8388608
    int nw4 = (ON * KD) / 4;  // 1048576
    convert_kernel<<<nx4 / 256, 256>>>(x, nx4, 0);
    convert_kernel<<<nw4 / 256, 256>>>(w, nw4, 1);

    dim3 grid(ON / BN, XN / BM);  // (16, 128): n-tiles fastest for W reuse in L2
    gemm_kernel<<<grid, 256, SMEM_TOTAL>>>(b, out);
}